// round 1
// baseline (speedup 1.0000x reference)
#include <cuda_runtime.h>
#include <math.h>

// Problem constants
#define BATCH 8
#define CH    512          // CIN == COUT == WDIM == 512
#define SIN_  64
#define SOUT  66           // conv output spatial (64 + 2*2 - 3 + 1)
#define SUP   138          // after 2x FIR upsample
#define TAPS  12

// ---------------- scratch (device globals; no allocations allowed) ----------
__device__ float g_styles[BATCH * CH];
__device__ float g_s[BATCH * CH];                 // normalized styles
__device__ float g_wt[(size_t)CH * CH * 9];       // per-o normalized conv weight
__device__ float g_A[CH * CH];                    // A[o][i] = sum_k wt^2
__device__ float g_d[BATCH * CH];                 // demod[b][o]
__device__ float g_y[(size_t)BATCH * CH * SOUT * SOUT]; // conv output (71.4 MB)

// ---------------- K1: styles = w @ (affine_w.T / sqrt(512)) + affine_b ------
__global__ void k_styles(const float* __restrict__ w,
                         const float* __restrict__ aw,
                         const float* __restrict__ ab) {
    int idx = blockIdx.x * blockDim.x + threadIdx.x;   // 0..4095
    int b = idx >> 9, c = idx & 511;
    const float* wr = w + b * 512;
    const float* ar = aw + c * 512;
    float acc = 0.f;
    #pragma unroll 8
    for (int d = 0; d < 512; d++) acc = fmaf(wr[d], ar[d], acc);
    g_styles[idx] = acc * 0.04419417382415922f + ab[c];
}

// ---------------- K2: s = styles * rsqrt(mean(styles^2)) (global mean) ------
__global__ void k_norm_styles() {
    __shared__ float red[256];
    float ss = 0.f;
    for (int i = threadIdx.x; i < 4096; i += 256) {
        float v = g_styles[i]; ss = fmaf(v, v, ss);
    }
    red[threadIdx.x] = ss; __syncthreads();
    for (int s = 128; s > 0; s >>= 1) {
        if (threadIdx.x < s) red[threadIdx.x] += red[threadIdx.x + s];
        __syncthreads();
    }
    float g = rsqrtf(red[0] * (1.0f / 4096.0f));
    for (int i = threadIdx.x; i < 4096; i += 256) g_s[i] = g_styles[i] * g;
}

// ---------------- K3: wt = conv_w * rsqrt(mean_o(conv_w^2)); A[o][i] --------
__global__ void k_wt(const float* __restrict__ cw) {
    int o = blockIdx.x;                   // 512 blocks
    const float* src = cw + (size_t)o * 4608;
    __shared__ float red[256];
    __shared__ float rsh;
    float ss = 0.f;
    for (int e = threadIdx.x; e < 4608; e += 256) {
        float v = src[e]; ss = fmaf(v, v, ss);
    }
    red[threadIdx.x] = ss; __syncthreads();
    for (int s = 128; s > 0; s >>= 1) {
        if (threadIdx.x < s) red[threadIdx.x] += red[threadIdx.x + s];
        __syncthreads();
    }
    if (threadIdx.x == 0) rsh = rsqrtf(red[0] * (1.0f / 4608.0f));
    __syncthreads();
    float r = rsh;
    for (int e = threadIdx.x; e < 4608; e += 256)
        g_wt[(size_t)o * 4608 + e] = src[e] * r;
    float r2 = r * r;
    for (int i = threadIdx.x; i < 512; i += 256) {
        float s9 = 0.f;
        #pragma unroll
        for (int k = 0; k < 9; k++) { float v = src[i * 9 + k]; s9 = fmaf(v, v, s9); }
        g_A[o * 512 + i] = s9 * r2;
    }
}

// ---------------- K4: d[b][o] = rsqrt(sum_i A[o][i]*s[b][i]^2 + 1e-8) -------
__global__ void k_demod() {
    int idx = blockIdx.x * 256 + threadIdx.x;  // 0..4095  (b*512+o)
    int b = idx >> 9, o = idx & 511;
    const float* Ao = g_A + o * 512;
    const float* sb = g_s + b * 512;
    float acc = 0.f;
    #pragma unroll 4
    for (int i = 0; i < 512; i++) { float sv = sb[i]; acc = fmaf(Ao[i], sv * sv, acc); }
    g_d[idx] = rsqrtf(acc + 1e-8f);
}

// ---------------- K5: main 3x3 conv, pad=2, shared weights ------------------
// y[b,o,r,c] = d[b,o] * sum_{i,ky,kx} wt[o,i,ky,kx] * (x[b,i,r+ky-2,c+kx-2]*s[b,i]) + cb[o]
// Tile: 64 out-ch x 8x8 spatial per block, 256 threads, 4o x 4cols per thread.
#define TO 64
#define CI 16
__global__ __launch_bounds__(256, 4) void k_conv(const float* __restrict__ x,
                                                 const float* __restrict__ cb) {
    __shared__ float xs[CI * 120];   // [ci][10 rows][pitch 12]
    __shared__ float ws[TO * 145];   // [o][ci*9], pitch 145 (bank-skew)
    int b    = blockIdx.z;
    int o0   = blockIdx.y * TO;
    int tile = blockIdx.x;           // 0..80 (9x9 tiles of 8x8 over 66x66)
    int row0 = (tile / 9) * 8, col0 = (tile % 9) * 8;
    int tid = threadIdx.x;
    int og = tid >> 4, sid = tid & 15;
    int r = sid >> 1, c4 = (sid & 1) * 4;

    float acc[4][4] = {};
    const float* sb = g_s + b * 512;

    for (int ci0 = 0; ci0 < 512; ci0 += CI) {
        __syncthreads();
        // stage x (with style modulation folded in), zero-padded
        for (int e = tid; e < CI * 100; e += 256) {
            int ci = e / 100, rr = (e % 100) / 10, cc = e % 10;
            int gr = row0 + rr - 2, gc = col0 + cc - 2;
            float v = 0.f;
            if ((unsigned)gr < 64u && (unsigned)gc < 64u)
                v = x[(((size_t)(b * 512 + ci0 + ci)) * 64 + gr) * 64 + gc] * sb[ci0 + ci];
            xs[ci * 120 + rr * 12 + cc] = v;
        }
        // stage weights
        for (int e = tid; e < TO * 144; e += 256) {
            int o = e / 144, rest = e % 144;
            ws[o * 145 + rest] = g_wt[(size_t)(o0 + o) * 4608 + (size_t)ci0 * 9 + rest];
        }
        __syncthreads();

        #pragma unroll 4
        for (int ci = 0; ci < CI; ci++) {
            #pragma unroll
            for (int ky = 0; ky < 3; ky++) {
                float xv[6];
                #pragma unroll
                for (int m = 0; m < 6; m++) xv[m] = xs[ci * 120 + (r + ky) * 12 + c4 + m];
                #pragma unroll
                for (int kx = 0; kx < 3; kx++) {
                    #pragma unroll
                    for (int j = 0; j < 4; j++) {
                        float wv = ws[(og * 4 + j) * 145 + ci * 9 + ky * 3 + kx];
                        #pragma unroll
                        for (int u = 0; u < 4; u++)
                            acc[j][u] = fmaf(wv, xv[kx + u], acc[j][u]);
                    }
                }
            }
        }
    }

    // epilogue: demod + bias, masked store
    int orow = row0 + r;
    if (orow < SOUT) {
        #pragma unroll
        for (int j = 0; j < 4; j++) {
            int o = o0 + og * 4 + j;
            float dm = g_d[b * 512 + o];
            float bias = cb[o];
            #pragma unroll
            for (int u = 0; u < 4; u++) {
                int ocol = col0 + c4 + u;
                if (ocol < SOUT)
                    g_y[(((size_t)(b * 512 + o)) * SOUT + orow) * SOUT + ocol]
                        = acc[j][u] * dm + bias;
            }
        }
    }
}

// ---------------- K6: fused 2x up-FIR -> act -> 2x down-FIR -----------------
// One block per (b, ch) image. Vup full image, then per row: Hup -> act -> Hdown,
// then Vdown (linear downs on different axes commute).
__global__ __launch_bounds__(256) void k_fir(const float* __restrict__ upf,
                                             const float* __restrict__ dnf,
                                             float* __restrict__ out) {
    extern __shared__ float sm[];
    float* sfu  = sm;                    // 12  (reversed, *2)
    float* sfd  = sm + 12;               // 12  (reversed)
    float* simg = sm + 24;               // 66*66 = 4356
    float* wbuf = simg + 4356;           // 8 warps * (66 + 138) = 1632
    float* smid = wbuf + 8 * 204;        // 138*64 = 8832
    int blk = blockIdx.x;                // b*512 + ch
    int tid = threadIdx.x;
    const float* src = g_y + (size_t)blk * (SOUT * SOUT);

    if (tid < 12) { sfu[tid] = 2.0f * upf[11 - tid]; sfd[tid] = dnf[11 - tid]; }
    for (int e = tid; e < SOUT * SOUT; e += 256) simg[e] = src[e];
    __syncthreads();

    int warp = tid >> 5, lane = tid & 31;
    float* vrow = wbuf + warp * 204;
    float* hrow = vrow + 66;

    for (int rr = warp; rr < SUP; rr += 8) {
        // vertical upsample row rr: j = rr + t - 9 must be even, 0..130
        int tv0 = (rr & 1) ^ 1;
        for (int c = lane; c < 66; c += 32) {
            float a = 0.f;
            for (int t = tv0; t < 12; t += 2) {
                int j = rr + t - 9;
                if (j >= 0 && j <= 130) a = fmaf(sfu[t], simg[(j >> 1) * 66 + c], a);
            }
            vrow[c] = a;
        }
        __syncwarp();
        // horizontal upsample + activation
        for (int q = lane; q < SUP; q += 32) {
            float a = 0.f;
            int t0 = (q & 1) ^ 1;
            for (int t = t0; t < 12; t += 2) {
                int j = q + t - 9;
                if (j >= 0 && j <= 130) a = fmaf(sfu[t], vrow[j >> 1], a);
            }
            a = (a >= 0.f ? a : 0.2f * a) * 1.4142135623730951f;
            a = fminf(fmaxf(a, -256.f), 256.f);
            hrow[q] = a;
        }
        __syncwarp();
        // horizontal downsample (stride 2)
        for (int p = lane; p < 64; p += 32) {
            float a = 0.f;
            #pragma unroll
            for (int t = 0; t < 12; t++) a = fmaf(sfd[t], hrow[2 * p + t], a);
            smid[rr * 64 + p] = a;
        }
        __syncwarp();
    }
    __syncthreads();

    // vertical downsample (stride 2) -> final 64x64
    float* dst = out + (size_t)blk * 4096;
    for (int e = tid; e < 4096; e += 256) {
        int p = e >> 6, c = e & 63;
        float a = 0.f;
        #pragma unroll
        for (int t = 0; t < 12; t++) a = fmaf(sfd[t], smid[(2 * p + t) * 64 + c], a);
        dst[e] = a;
    }
}

// ---------------- launch -----------------------------------------------------
extern "C" void kernel_launch(void* const* d_in, const int* in_sizes, int n_in,
                              void* d_out, int out_size) {
    const float* x  = (const float*)d_in[0];
    const float* w  = (const float*)d_in[1];
    const float* aw = (const float*)d_in[2];
    const float* ab = (const float*)d_in[3];
    const float* cw = (const float*)d_in[4];
    const float* cb = (const float*)d_in[5];
    const float* uf = (const float*)d_in[6];
    const float* df = (const float*)d_in[7];
    float* out = (float*)d_out;

    k_styles<<<16, 256>>>(w, aw, ab);
    k_norm_styles<<<1, 256>>>();
    k_wt<<<512, 256>>>(cw);
    k_demod<<<16, 256>>>();

    dim3 cgrid(81, CH / TO, BATCH);   // 81 x 8 x 8 = 5184 blocks
    k_conv<<<cgrid, 256>>>(x, cb);

    const int fir_smem = (24 + 4356 + 8 * 204 + 8832) * (int)sizeof(float); // 59376 B
    cudaFuncSetAttribute(k_fir, cudaFuncAttributeMaxDynamicSharedMemorySize, fir_smem);
    k_fir<<<BATCH * CH, 256, fir_smem>>>(uf, df, out);
}

// round 2
// speedup vs baseline: 1.2312x; 1.2312x over previous
#include <cuda_runtime.h>
#include <math.h>

// Problem constants
#define BATCH 8
#define CH    512
#define SOUT  66           // conv output spatial (64 + 2*2 - 3 + 1)
#define SUP   138          // after 2x FIR upsample
#define TAPS  12

typedef unsigned long long ull;

// ---------------- scratch (device globals) ----------------------------------
__device__ float g_styles[BATCH * CH];
__device__ float g_s[BATCH * CH];                    // normalized styles
__device__ float g_wtT[(size_t)CH * 9 * CH];         // transposed: [(i*9+k)][o]
__device__ float g_A[CH * CH];                       // A[o][i] = sum_k wt^2
__device__ float g_d[BATCH * CH];                    // demod[b][o]
__device__ float g_y[(size_t)BATCH * CH * SOUT * SOUT]; // raw conv acc (71.4 MB)

// ---------------- f32x2 helpers ----------------------------------------------
__device__ __forceinline__ ull pack2(float lo, float hi) {
    ull r; asm("mov.b64 %0, {%1,%2};" : "=l"(r) : "f"(lo), "f"(hi)); return r;
}
__device__ __forceinline__ void unpack2(ull v, float& lo, float& hi) {
    asm("mov.b64 {%0,%1}, %2;" : "=f"(lo), "=f"(hi) : "l"(v));
}
__device__ __forceinline__ void fma2(ull& d, ull a, ull b) {
    asm("fma.rn.f32x2 %0, %1, %2, %0;" : "+l"(d) : "l"(a), "l"(b));
}

// ---------------- K1: styles = w @ (affine_w.T / sqrt(512)) + affine_b ------
// warp per output; grid 512 x 256
__global__ void k_styles(const float* __restrict__ w,
                         const float* __restrict__ aw,
                         const float* __restrict__ ab) {
    int wid = (blockIdx.x * 256 + threadIdx.x) >> 5;   // 0..4095
    int lane = threadIdx.x & 31;
    int b = wid >> 9, c = wid & 511;
    const float* wr = w + b * 512;
    const float* ar = aw + c * 512;
    float acc = 0.f;
    #pragma unroll 4
    for (int d = lane; d < 512; d += 32) acc = fmaf(wr[d], ar[d], acc);
    #pragma unroll
    for (int s = 16; s; s >>= 1) acc += __shfl_xor_sync(0xFFFFFFFFu, acc, s);
    if (lane == 0) g_styles[wid] = acc * 0.04419417382415922f + ab[c];
}

// ---------------- K2: s = styles * rsqrt(mean(styles^2)) --------------------
__global__ void k_norm_styles() {
    __shared__ float red[256];
    float ss = 0.f;
    for (int i = threadIdx.x; i < 4096; i += 256) {
        float v = g_styles[i]; ss = fmaf(v, v, ss);
    }
    red[threadIdx.x] = ss; __syncthreads();
    for (int s = 128; s > 0; s >>= 1) {
        if (threadIdx.x < s) red[threadIdx.x] += red[threadIdx.x + s];
        __syncthreads();
    }
    float g = rsqrtf(red[0] * (1.0f / 4096.0f));
    for (int i = threadIdx.x; i < 4096; i += 256) g_s[i] = g_styles[i] * g;
}

// ---------------- K3: wt normalize -> transposed layout; A[o][i] ------------
__global__ void k_wt(const float* __restrict__ cw) {
    int o = blockIdx.x;                   // 512 blocks
    const float* src = cw + (size_t)o * 4608;
    __shared__ float red[256];
    __shared__ float rsh;
    float ss = 0.f;
    for (int e = threadIdx.x; e < 4608; e += 256) {
        float v = src[e]; ss = fmaf(v, v, ss);
    }
    red[threadIdx.x] = ss; __syncthreads();
    for (int s = 128; s > 0; s >>= 1) {
        if (threadIdx.x < s) red[threadIdx.x] += red[threadIdx.x + s];
        __syncthreads();
    }
    if (threadIdx.x == 0) rsh = rsqrtf(red[0] * (1.0f / 4608.0f));
    __syncthreads();
    float r = rsh;
    for (int e = threadIdx.x; e < 4608; e += 256)
        g_wtT[(size_t)e * 512 + o] = src[e] * r;      // transposed write
    float r2 = r * r;
    for (int i = threadIdx.x; i < 512; i += 256) {
        float s9 = 0.f;
        #pragma unroll
        for (int k = 0; k < 9; k++) { float v = src[i * 9 + k]; s9 = fmaf(v, v, s9); }
        g_A[o * 512 + i] = s9 * r2;
    }
}

// ---------------- K4: d[b][o] = rsqrt(sum_i A[o][i]*s[b][i]^2 + 1e-8) -------
// warp per output; grid 512 x 256
__global__ void k_demod() {
    int wid = (blockIdx.x * 256 + threadIdx.x) >> 5;   // 0..4095 (b*512+o)
    int lane = threadIdx.x & 31;
    int b = wid >> 9, o = wid & 511;
    const float* Ao = g_A + o * 512;
    const float* sb = g_s + b * 512;
    float acc = 0.f;
    #pragma unroll 4
    for (int i = lane; i < 512; i += 32) {
        float sv = sb[i]; acc = fmaf(Ao[i], sv * sv, acc);
    }
    #pragma unroll
    for (int s = 16; s; s >>= 1) acc += __shfl_xor_sync(0xFFFFFFFFu, acc, s);
    if (lane == 0) g_d[wid] = rsqrtf(acc + 1e-8f);
}

// ---------------- K5: main 3x3 conv (pad=2) with f32x2 packed FMA -----------
// acc[b,o,r,c] = sum_{i,ky,kx} wt[o,i,ky,kx] * (x[b,i,r+ky-2,c+kx-2]*s[b,i])
// Tile: 64 out-ch x 8x8 spatial, 256 threads.
// Thread: og = tid&15 (4 o's: og*4 + {0,1,2,3} as two f32x2 pairs), sid = tid>>4.
#define TO 64
#define CI 16
__global__ __launch_bounds__(256, 3) void k_conv(const float* __restrict__ x) {
    __shared__ float xs[CI * 120];     // [ci][10 rows][pitch 12]   7.7 KB
    __shared__ float ws2[144 * 64];    // [ci*9+kk][o0..o63]        36.9 KB
    int b    = blockIdx.z;
    int o0   = blockIdx.y * TO;
    int tile = blockIdx.x;             // 0..80 (9x9 tiles of 8x8 over 66x66)
    int row0 = (tile / 9) * 8, col0 = (tile % 9) * 8;
    int tid  = threadIdx.x;
    int og   = tid & 15;
    int sid  = tid >> 4;
    int r    = sid >> 1, c4 = (sid & 1) * 4;

    ull acc[2][4];
    #pragma unroll
    for (int j = 0; j < 2; j++)
        #pragma unroll
        for (int u = 0; u < 4; u++) acc[j][u] = 0ull;

    const float* sb = g_s + b * 512;

    for (int ci0 = 0; ci0 < 512; ci0 += CI) {
        __syncthreads();
        // stage x (style folded in), zero-padded halo
        for (int e = tid; e < CI * 100; e += 256) {
            int ci = e / 100, rr = (e % 100) / 10, cc = e % 10;
            int gr = row0 + rr - 2, gc = col0 + cc - 2;
            float v = 0.f;
            if ((unsigned)gr < 64u && (unsigned)gc < 64u)
                v = x[(((size_t)(b * 512 + ci0 + ci)) * 64 + gr) * 64 + gc] * sb[ci0 + ci];
            xs[ci * 120 + rr * 12 + cc] = v;
        }
        // stage weights (already transposed in global: coalesced)
        {
            const float* wsrc = g_wtT + (size_t)(ci0 * 9) * 512 + o0;
            for (int e = tid; e < 144 * 64; e += 256)
                ws2[e] = wsrc[(size_t)(e >> 6) * 512 + (e & 63)];
        }
        __syncthreads();

        #pragma unroll 2
        for (int ci = 0; ci < CI; ci++) {
            const float* xrow = &xs[ci * 120];
            #pragma unroll
            for (int ky = 0; ky < 3; ky++) {
                ull xd[6];
                #pragma unroll
                for (int m = 0; m < 6; m++) {
                    float v = xrow[(r + ky) * 12 + c4 + m];
                    xd[m] = pack2(v, v);
                }
                #pragma unroll
                for (int kx = 0; kx < 3; kx++) {
                    const float* wrow = &ws2[(ci * 9 + ky * 3 + kx) * 64 + og * 4];
                    ull w0 = *(const ull*)(wrow);
                    ull w1 = *(const ull*)(wrow + 2);
                    #pragma unroll
                    for (int u = 0; u < 4; u++) {
                        fma2(acc[0][u], w0, xd[kx + u]);
                        fma2(acc[1][u], w1, xd[kx + u]);
                    }
                }
            }
        }
    }

    // epilogue: store raw acc (demod+bias applied in k_fir), float2 stores
    int orow = row0 + r;
    if (orow < SOUT) {
        #pragma unroll
        for (int jp = 0; jp < 2; jp++) {
            int o = o0 + og * 4 + jp * 2;
            size_t base0 = (((size_t)(b * 512 + o)) * SOUT + orow) * SOUT;
            size_t base1 = base0 + (size_t)SOUT * SOUT;
            #pragma unroll
            for (int p = 0; p < 2; p++) {           // col pairs (0,1),(2,3)
                int oc = col0 + c4 + 2 * p;
                if (oc + 1 < SOUT + 1 && oc < SOUT - 1 + 1 && oc <= SOUT - 2) {
                    float l0, h0, l1, h1;
                    unpack2(acc[jp][2 * p],     l0, h0);
                    unpack2(acc[jp][2 * p + 1], l1, h1);
                    *(float2*)&g_y[base0 + oc] = make_float2(l0, l1);
                    *(float2*)&g_y[base1 + oc] = make_float2(h0, h1);
                }
            }
        }
    }
}

// ---------------- K6: demod+bias -> 2x up-FIR -> act -> 2x down-FIR ---------
__global__ __launch_bounds__(256) void k_fir(const float* __restrict__ upf,
                                             const float* __restrict__ dnf,
                                             const float* __restrict__ cb,
                                             float* __restrict__ out) {
    extern __shared__ float sm[];
    float* sfu  = sm;                    // 12  (reversed, *2)
    float* sfd  = sm + 12;               // 12  (reversed)
    float* simg = sm + 24;               // 66*66 = 4356
    float* wbuf = simg + 4356;           // 8 warps * (66 + 138) = 1632
    float* smid = wbuf + 8 * 204;        // 138*64 = 8832
    int blk = blockIdx.x;                // b*512 + ch
    int tid = threadIdx.x;
    const float* src = g_y + (size_t)blk * (SOUT * SOUT);
    float dm = g_d[blk];
    float bias = cb[blk & 511];

    if (tid < 12) { sfu[tid] = 2.0f * upf[11 - tid]; sfd[tid] = dnf[11 - tid]; }
    for (int e = tid; e < SOUT * SOUT; e += 256) simg[e] = src[e] * dm + bias;
    __syncthreads();

    int warp = tid >> 5, lane = tid & 31;
    float* vrow = wbuf + warp * 204;
    float* hrow = vrow + 66;

    for (int rr = warp; rr < SUP; rr += 8) {
        int tv0 = (rr & 1) ^ 1;
        for (int c = lane; c < 66; c += 32) {
            float a = 0.f;
            for (int t = tv0; t < 12; t += 2) {
                int j = rr + t - 9;
                if (j >= 0 && j <= 130) a = fmaf(sfu[t], simg[(j >> 1) * 66 + c], a);
            }
            vrow[c] = a;
        }
        __syncwarp();
        for (int q = lane; q < SUP; q += 32) {
            float a = 0.f;
            int t0 = (q & 1) ^ 1;
            for (int t = t0; t < 12; t += 2) {
                int j = q + t - 9;
                if (j >= 0 && j <= 130) a = fmaf(sfu[t], vrow[j >> 1], a);
            }
            a = (a >= 0.f ? a : 0.2f * a) * 1.4142135623730951f;
            a = fminf(fmaxf(a, -256.f), 256.f);
            hrow[q] = a;
        }
        __syncwarp();
        for (int p = lane; p < 64; p += 32) {
            float a = 0.f;
            #pragma unroll
            for (int t = 0; t < 12; t++) a = fmaf(sfd[t], hrow[2 * p + t], a);
            smid[rr * 64 + p] = a;
        }
        __syncwarp();
    }
    __syncthreads();

    float* dst = out + (size_t)blk * 4096;
    for (int e = tid; e < 4096; e += 256) {
        int p = e >> 6, c = e & 63;
        float a = 0.f;
        #pragma unroll
        for (int t = 0; t < 12; t++) a = fmaf(sfd[t], smid[(2 * p + t) * 64 + c], a);
        dst[e] = a;
    }
}

// ---------------- launch -----------------------------------------------------
extern "C" void kernel_launch(void* const* d_in, const int* in_sizes, int n_in,
                              void* d_out, int out_size) {
    const float* x  = (const float*)d_in[0];
    const float* w  = (const float*)d_in[1];
    const float* aw = (const float*)d_in[2];
    const float* ab = (const float*)d_in[3];
    const float* cw = (const float*)d_in[4];
    const float* cb = (const float*)d_in[5];
    const float* uf = (const float*)d_in[6];
    const float* df = (const float*)d_in[7];
    float* out = (float*)d_out;

    k_styles<<<512, 256>>>(w, aw, ab);          // 1
    k_norm_styles<<<1, 256>>>();                // 2
    k_wt<<<512, 256>>>(cw);                     // 3

    dim3 cgrid(81, CH / TO, BATCH);             // 4  <-- profiled slot
    k_conv<<<cgrid, 256>>>(x);

    k_demod<<<512, 256>>>();                    // 5

    const int fir_smem = (24 + 4356 + 8 * 204 + 8832) * (int)sizeof(float);
    cudaFuncSetAttribute(k_fir, cudaFuncAttributeMaxDynamicSharedMemorySize, fir_smem);
    k_fir<<<BATCH * CH, 256, fir_smem>>>(uf, df, cb, out); // 6
}

// round 5
// speedup vs baseline: 2.3136x; 1.8791x over previous
#include <cuda_runtime.h>
#include <math.h>

#define BATCH 8
#define CH    512
#define NPIX  4356          // 66*66
#define SUP   138
#define KTOT  4608

typedef unsigned int u32;

// ---------------- scratch (device globals; 16B-aligned for float4) ----------
__device__ float g_styles[BATCH * CH];
__device__ float g_s[BATCH * CH];
__device__ __align__(16) float g_xs[(size_t)BATCH * CH * 4096];   // tf32(x*s)
__device__ __align__(16) float g_wtB[(size_t)CH * KTOT];          // tf32(wt) [o][k]
__device__ float g_A[CH * CH];
__device__ float g_d[BATCH * CH];
__device__ __align__(16) float g_y[(size_t)BATCH * CH * NPIX];    // conv out [b][o][p]

__device__ __forceinline__ u32 cvt_tf32(float v) {
    u32 u; asm("cvt.rna.tf32.f32 %0, %1;" : "=r"(u) : "f"(v)); return u;
}
__device__ __forceinline__ void mma_tf32(float* c, u32 a0, u32 a1, u32 a2, u32 a3,
                                         u32 b0, u32 b1) {
    asm volatile("mma.sync.aligned.m16n8k8.row.col.f32.tf32.tf32.f32 "
        "{%0,%1,%2,%3}, {%4,%5,%6,%7}, {%8,%9}, {%0,%1,%2,%3};"
        : "+f"(c[0]), "+f"(c[1]), "+f"(c[2]), "+f"(c[3])
        : "r"(a0), "r"(a1), "r"(a2), "r"(a3), "r"(b0), "r"(b1));
}

// ---------------- K1: styles -------------------------------------------------
__global__ void k_styles(const float* __restrict__ w,
                         const float* __restrict__ aw,
                         const float* __restrict__ ab) {
    int wid = (blockIdx.x * 256 + threadIdx.x) >> 5;
    int lane = threadIdx.x & 31;
    int b = wid >> 9, c = wid & 511;
    const float* wr = w + b * 512;
    const float* ar = aw + c * 512;
    float acc = 0.f;
    #pragma unroll 4
    for (int d = lane; d < 512; d += 32) acc = fmaf(wr[d], ar[d], acc);
    #pragma unroll
    for (int s = 16; s; s >>= 1) acc += __shfl_xor_sync(0xFFFFFFFFu, acc, s);
    if (lane == 0) g_styles[wid] = acc * 0.04419417382415922f + ab[c];
}

// ---------------- K2: normalize styles --------------------------------------
__global__ void k_norm_styles() {
    __shared__ float red[256];
    float ss = 0.f;
    for (int i = threadIdx.x; i < 4096; i += 256) {
        float v = g_styles[i]; ss = fmaf(v, v, ss);
    }
    red[threadIdx.x] = ss; __syncthreads();
    for (int s = 128; s > 0; s >>= 1) {
        if (threadIdx.x < s) red[threadIdx.x] += red[threadIdx.x + s];
        __syncthreads();
    }
    float g = rsqrtf(red[0] * (1.0f / 4096.0f));
    for (int i = threadIdx.x; i < 4096; i += 256) g_s[i] = g_styles[i] * g;
}

// ---------------- K2b: prescale x -> tf32(x*s) -------------------------------
__global__ void k_xs(const float* __restrict__ x) {
    int f4 = blockIdx.x * 256 + threadIdx.x;          // 0 .. 4.19M-1
    int cf = f4 >> 10;                                // b*512+ci
    float s = g_s[cf];
    float4 v = ((const float4*)x)[f4];
    float4 o;
    o.x = __uint_as_float(cvt_tf32(v.x * s));
    o.y = __uint_as_float(cvt_tf32(v.y * s));
    o.z = __uint_as_float(cvt_tf32(v.z * s));
    o.w = __uint_as_float(cvt_tf32(v.w * s));
    ((float4*)g_xs)[f4] = o;
}

// ---------------- K3: wt normalize -> tf32 [o][k]; A[o][i] -------------------
__global__ void k_wt(const float* __restrict__ cw) {
    int o = blockIdx.x;
    const float* src = cw + (size_t)o * KTOT;
    __shared__ float red[256];
    __shared__ float rsh;
    float ss = 0.f;
    for (int e = threadIdx.x; e < KTOT; e += 256) {
        float v = src[e]; ss = fmaf(v, v, ss);
    }
    red[threadIdx.x] = ss; __syncthreads();
    for (int s = 128; s > 0; s >>= 1) {
        if (threadIdx.x < s) red[threadIdx.x] += red[threadIdx.x + s];
        __syncthreads();
    }
    if (threadIdx.x == 0) rsh = rsqrtf(red[0] * (1.0f / 4608.0f));
    __syncthreads();
    float r = rsh;
    for (int e = threadIdx.x; e < KTOT; e += 256)
        g_wtB[(size_t)o * KTOT + e] = __uint_as_float(cvt_tf32(src[e] * r));
    float r2 = r * r;
    for (int i = threadIdx.x; i < 512; i += 256) {
        float s9 = 0.f;
        #pragma unroll
        for (int k = 0; k < 9; k++) { float v = src[i * 9 + k]; s9 = fmaf(v, v, s9); }
        g_A[o * 512 + i] = s9 * r2;
    }
}

// ---------------- K5: mma.sync tf32 implicit-GEMM conv -----------------------
// Block: 128 pixels x 128 outs; 8 warps (4m x 2n), warp tile 32x64.
// K in 144 chunks of 32. A frags gathered from a 5ci x 5row x 70col halo.
__global__ __launch_bounds__(256, 2) void k_conv() {
    __shared__ __align__(16) float Hs[1752];   // halo [dci][ry][cx] (tf32 bits)
    __shared__ __align__(16) float Bs[128 * 36]; // [o][k] pitch 36  (tf32 bits)
    const u32* Hu = (const u32*)Hs;
    const u32* Bu = (const u32*)Bs;

    int tid = threadIdx.x, wid = tid >> 5, lane = tid & 31;
    int g = lane >> 2, tg = lane & 3;
    int wm = wid & 3, wn = wid >> 2;
    int b = blockIdx.z;
    int p0 = blockIdx.x * 128, o0 = blockIdx.y * 128;
    int r_min = p0 / 66;

    int baseA[2][2];
    bool pok[2][2];
    #pragma unroll
    for (int mt = 0; mt < 2; mt++)
        #pragma unroll
        for (int h = 0; h < 2; h++) {
            int p = p0 + wm * 32 + mt * 16 + h * 8 + g;
            bool ok = p < NPIX;
            int r = p / 66, c = p - r * 66;
            baseA[mt][h] = ok ? ((r - r_min) * 70 + c) : 0;
            pok[mt][h] = ok;
        }

    float acc[2][8][4];
    #pragma unroll
    for (int mt = 0; mt < 2; mt++)
        #pragma unroll
        for (int nt = 0; nt < 8; nt++)
            #pragma unroll
            for (int q = 0; q < 4; q++) acc[mt][nt][q] = 0.f;

    const float* xsb = g_xs + ((size_t)b << 21);

    for (int i = 0; i < 144; i++) {
        int k0 = i * 32;
        int ci_lo = k0 / 9;

        #pragma unroll 1
        for (int e = tid; e < 1750; e += 256) {
            int dci = e / 350; int rem = e - dci * 350;
            int ry = rem / 70;  int cx = rem - ry * 70;
            int ci = ci_lo + dci;
            int gr = r_min - 2 + ry, gc = cx - 2;
            float v = 0.f;
            if (ci < 512 && (unsigned)gr < 64u && (unsigned)gc < 64u)
                v = xsb[((size_t)ci << 12) + (gr << 6) + gc];
            Hs[e] = v;
        }
        #pragma unroll
        for (int q = 0; q < 4; q++) {
            int idx = tid + q * 256;
            int row = idx >> 3, seg = idx & 7;
            float4 v = *(const float4*)&g_wtB[(size_t)(o0 + row) * KTOT + k0 + seg * 4];
            *(float4*)&Bs[row * 36 + seg * 4] = v;
        }
        __syncthreads();

        u32 offs[4][2];
        #pragma unroll
        for (int ks = 0; ks < 4; ks++)
            #pragma unroll
            for (int h = 0; h < 2; h++) {
                int kg = k0 + ks * 8 + h * 4 + tg;
                int ci = kg / 9; int t9 = kg - 9 * ci;
                int ky = t9 / 3; int kx = t9 - 3 * ky;
                offs[ks][h] = (u32)((ci - ci_lo) * 350 + ky * 70 + kx);
            }

        #pragma unroll
        for (int ks = 0; ks < 4; ks++) {
            u32 bf0[8], bf1[8];
            int kb = ks * 8 + tg;
            #pragma unroll
            for (int nt = 0; nt < 8; nt++) {
                int n = wn * 64 + nt * 8 + g;
                bf0[nt] = Bu[n * 36 + kb];
                bf1[nt] = Bu[n * 36 + kb + 4];
            }
            #pragma unroll
            for (int mt = 0; mt < 2; mt++) {
                u32 a0 = Hu[baseA[mt][0] + offs[ks][0]];
                u32 a1 = Hu[baseA[mt][1] + offs[ks][0]];
                u32 a2 = Hu[baseA[mt][0] + offs[ks][1]];
                u32 a3 = Hu[baseA[mt][1] + offs[ks][1]];
                #pragma unroll
                for (int nt = 0; nt < 8; nt++)
                    mma_tf32(acc[mt][nt], a0, a1, a2, a3, bf0[nt], bf1[nt]);
            }
        }
        __syncthreads();
    }

    #pragma unroll
    for (int mt = 0; mt < 2; mt++) {
        int prow0 = p0 + wm * 32 + mt * 16 + g;
        #pragma unroll
        for (int nt = 0; nt < 8; nt++) {
            int o = o0 + wn * 64 + nt * 8 + 2 * tg;
            size_t bo = ((size_t)(b * 512 + o)) * NPIX;
            if (pok[mt][0]) {
                g_y[bo + prow0] = acc[mt][nt][0];
                g_y[bo + NPIX + prow0] = acc[mt][nt][1];
            }
            if (pok[mt][1]) {
                g_y[bo + prow0 + 8] = acc[mt][nt][2];
                g_y[bo + NPIX + prow0 + 8] = acc[mt][nt][3];
            }
        }
    }
}

// ---------------- K4: demod --------------------------------------------------
__global__ void k_demod() {
    int wid = (blockIdx.x * 256 + threadIdx.x) >> 5;
    int lane = threadIdx.x & 31;
    int b = wid >> 9, o = wid & 511;
    const float* Ao = g_A + o * 512;
    const float* sbp = g_s + b * 512;
    float acc = 0.f;
    #pragma unroll 4
    for (int i = lane; i < 512; i += 32) {
        float sv = sbp[i]; acc = fmaf(Ao[i], sv * sv, acc);
    }
    #pragma unroll
    for (int s = 16; s; s >>= 1) acc += __shfl_xor_sync(0xFFFFFFFFu, acc, s);
    if (lane == 0) g_d[wid] = rsqrtf(acc + 1e-8f);
}

// ---------------- K6: demod+bias -> up-FIR -> act -> down-FIR ----------------
__global__ __launch_bounds__(256) void k_fir(const float* __restrict__ upf,
                                             const float* __restrict__ dnf,
                                             const float* __restrict__ cb,
                                             float* __restrict__ out) {
    extern __shared__ float sm[];
    float* sfu  = sm;
    float* sfd  = sm + 12;
    float* simg = sm + 24;
    float* wbuf = simg + 4356;
    float* smid = wbuf + 8 * 204;
    int blk = blockIdx.x;
    int tid = threadIdx.x;
    const float* src = g_y + (size_t)blk * NPIX;
    float dm = g_d[blk];
    float bias = cb[blk & 511];

    if (tid < 12) { sfu[tid] = 2.0f * upf[11 - tid]; sfd[tid] = dnf[11 - tid]; }
    for (int e = tid; e < NPIX; e += 256) simg[e] = src[e] * dm + bias;
    __syncthreads();

    int warp = tid >> 5, lane = tid & 31;
    float* vrow = wbuf + warp * 204;
    float* hrow = vrow + 66;

    for (int rr = warp; rr < SUP; rr += 8) {
        int tv0 = (rr & 1) ^ 1;
        for (int c = lane; c < 66; c += 32) {
            float a = 0.f;
            for (int t = tv0; t < 12; t += 2) {
                int j = rr + t - 9;
                if (j >= 0 && j <= 130) a = fmaf(sfu[t], simg[(j >> 1) * 66 + c], a);
            }
            vrow[c] = a;
        }
        __syncwarp();
        for (int q = lane; q < SUP; q += 32) {
            float a = 0.f;
            int t0 = (q & 1) ^ 1;
            for (int t = t0; t < 12; t += 2) {
                int j = q + t - 9;
                if (j >= 0 && j <= 130) a = fmaf(sfu[t], vrow[j >> 1], a);
            }
            a = (a >= 0.f ? a : 0.2f * a) * 1.4142135623730951f;
            a = fminf(fmaxf(a, -256.f), 256.f);
            hrow[q] = a;
        }
        __syncwarp();
        for (int p2 = lane; p2 < 64; p2 += 32) {
            float a = 0.f;
            #pragma unroll
            for (int t = 0; t < 12; t++) a = fmaf(sfd[t], hrow[2 * p2 + t], a);
            smid[rr * 64 + p2] = a;
        }
        __syncwarp();
    }
    __syncthreads();

    float* dst = out + (size_t)blk * 4096;
    for (int e = tid; e < 4096; e += 256) {
        int p2 = e >> 6, c = e & 63;
        float a = 0.f;
        #pragma unroll
        for (int t = 0; t < 12; t++) a = fmaf(sfd[t], smid[(2 * p2 + t) * 64 + c], a);
        dst[e] = a;
    }
}

// ---------------- launch -----------------------------------------------------
extern "C" void kernel_launch(void* const* d_in, const int* in_sizes, int n_in,
                              void* d_out, int out_size) {
    const float* x  = (const float*)d_in[0];
    const float* w  = (const float*)d_in[1];
    const float* aw = (const float*)d_in[2];
    const float* ab = (const float*)d_in[3];
    const float* cw = (const float*)d_in[4];
    const float* cb = (const float*)d_in[5];
    const float* uf = (const float*)d_in[6];
    const float* df = (const float*)d_in[7];
    float* out = (float*)d_out;

    k_styles<<<512, 256>>>(w, aw, ab);              // 1
    k_norm_styles<<<1, 256>>>();                    // 2
    k_xs<<<16384, 256>>>(x);                        // 3 (before conv)
    k_wt<<<512, 256>>>(cw);                         // 4

    dim3 cgrid(35, 4, BATCH);
    k_conv<<<cgrid, 256>>>();                       // 5

    k_demod<<<512, 256>>>();                        // 6

    const int fir_smem = (24 + 4356 + 8 * 204 + 8832) * (int)sizeof(float);
    cudaFuncSetAttribute(k_fir, cudaFuncAttributeMaxDynamicSharedMemorySize, fir_smem);
    k_fir<<<BATCH * CH, 256, fir_smem>>>(uf, df, cb, out); // 7
}

// round 6
// speedup vs baseline: 2.6852x; 1.1606x over previous
#include <cuda_runtime.h>
#include <cuda_fp16.h>
#include <math.h>

#define BATCH 8
#define CH    512
#define NPIX  4356          // 66*66
#define SUP   138
#define KTOT  4608
#define PA    40            // smem tile pitch in halves (80B rows, LDSM conflict-free)

typedef unsigned int u32;

// ---------------- scratch (device globals) ----------------------------------
__device__ float g_styles[BATCH * CH];
__device__ float g_s[BATCH * CH];
__device__ __align__(16) __half g_xs[(size_t)BATCH * CH * 4096];  // half(x*s)
__device__ __align__(16) __half g_wtB[(size_t)CH * KTOT];         // half(wt) [o][k]
__device__ float g_A[CH * CH];
__device__ float g_d[BATCH * CH];
__device__ __align__(16) float g_y[(size_t)BATCH * CH * NPIX];    // conv out [b][o][p]

__device__ __forceinline__ void ldsm4(u32& r0, u32& r1, u32& r2, u32& r3, u32 addr) {
    asm volatile("ldmatrix.sync.aligned.m8n8.x4.shared.b16 {%0,%1,%2,%3}, [%4];"
        : "=r"(r0), "=r"(r1), "=r"(r2), "=r"(r3) : "r"(addr));
}
__device__ __forceinline__ void mma_f16(float* c, u32 a0, u32 a1, u32 a2, u32 a3,
                                        u32 b0, u32 b1) {
    asm volatile("mma.sync.aligned.m16n8k16.row.col.f32.f16.f16.f32 "
        "{%0,%1,%2,%3}, {%4,%5,%6,%7}, {%8,%9}, {%0,%1,%2,%3};"
        : "+f"(c[0]), "+f"(c[1]), "+f"(c[2]), "+f"(c[3])
        : "r"(a0), "r"(a1), "r"(a2), "r"(a3), "r"(b0), "r"(b1));
}
__device__ __forceinline__ u32 smem_u32(const void* p) {
    u32 a; asm("{ .reg .u64 t; cvta.to.shared.u64 t, %1; cvt.u32.u64 %0, t; }"
               : "=r"(a) : "l"(p));
    return a;
}

// ---------------- K1 (merged): wt-normalize part + styles part --------------
__global__ void k_pre(const float* __restrict__ cw,
                      const float* __restrict__ w,
                      const float* __restrict__ aw,
                      const float* __restrict__ ab) {
    __shared__ float red[256];
    __shared__ float rsh;
    if (blockIdx.x < 512) {
        // ---- wt part ----
        int o = blockIdx.x;
        const float* src = cw + (size_t)o * KTOT;
        float ss = 0.f;
        for (int e = threadIdx.x; e < KTOT; e += 256) {
            float v = src[e]; ss = fmaf(v, v, ss);
        }
        red[threadIdx.x] = ss; __syncthreads();
        for (int s = 128; s > 0; s >>= 1) {
            if (threadIdx.x < s) red[threadIdx.x] += red[threadIdx.x + s];
            __syncthreads();
        }
        if (threadIdx.x == 0) rsh = rsqrtf(red[0] * (1.0f / 4608.0f));
        __syncthreads();
        float r = rsh;
        for (int e = threadIdx.x; e < KTOT; e += 256)
            g_wtB[(size_t)o * KTOT + e] = __float2half_rn(src[e] * r);
        float r2 = r * r;
        for (int i = threadIdx.x; i < 512; i += 256) {
            float s9 = 0.f;
            #pragma unroll
            for (int k = 0; k < 9; k++) { float v = src[i * 9 + k]; s9 = fmaf(v, v, s9); }
            g_A[o * 512 + i] = s9 * r2;
        }
    } else {
        // ---- styles part ----
        int wid = ((blockIdx.x - 512) * 256 + threadIdx.x) >> 5;  // 0..4095
        int lane = threadIdx.x & 31;
        int b = wid >> 9, c = wid & 511;
        const float* wr = w + b * 512;
        const float* ar = aw + c * 512;
        float acc = 0.f;
        #pragma unroll 4
        for (int d = lane; d < 512; d += 32) acc = fmaf(wr[d], ar[d], acc);
        #pragma unroll
        for (int s = 16; s; s >>= 1) acc += __shfl_xor_sync(0xFFFFFFFFu, acc, s);
        if (lane == 0) g_styles[wid] = acc * 0.04419417382415922f + ab[c];
    }
}

// ---------------- K2: normalize styles --------------------------------------
__global__ void k_norm_styles() {
    __shared__ float red[256];
    float ss = 0.f;
    for (int i = threadIdx.x; i < 4096; i += 256) {
        float v = g_styles[i]; ss = fmaf(v, v, ss);
    }
    red[threadIdx.x] = ss; __syncthreads();
    for (int s = 128; s > 0; s >>= 1) {
        if (threadIdx.x < s) red[threadIdx.x] += red[threadIdx.x + s];
        __syncthreads();
    }
    float g = rsqrtf(red[0] * (1.0f / 4096.0f));
    for (int i = threadIdx.x; i < 4096; i += 256) g_s[i] = g_styles[i] * g;
}

// ---------------- K3: prescale x -> half(x*s) --------------------------------
__global__ void k_xs(const float* __restrict__ x) {
    int i = blockIdx.x * 256 + threadIdx.x;   // over 8,388,608 float2
    float2 v = ((const float2*)x)[i];
    int cf = i >> 11;                         // channel-image = 2048 float2
    float s = g_s[cf];
    ((__half2*)g_xs)[i] = __floats2half2_rn(v.x * s, v.y * s);
}

// ---------------- K4: fp16 mma.m16n8k16 implicit-GEMM conv -------------------
// Block: 128 pixels x 128 outs; 8 warps (4m x 2n), warp tile 32x64.
// K in 144 chunks of 32.  A gathered via halo -> A-tile; frags via ldmatrix.
__global__ __launch_bounds__(256, 2) void k_conv() {
    __shared__ __align__(16) __half Hs[1792];        // halo [dci<5][ry<5][cx<70]
    __shared__ __align__(16) __half As[128 * PA];    // [pix][k]  pitch 40
    __shared__ __align__(16) __half Bs[128 * PA];    // [o][k]    pitch 40
    __shared__ u32 offs_sh[32];

    int tid = threadIdx.x, wid = tid >> 5, lane = tid & 31;
    int g = lane >> 2, tg = lane & 3;
    int wm = wid & 3, wn = wid >> 2;
    int b = blockIdx.z;
    int p0 = blockIdx.x * 128, o0 = blockIdx.y * 128;
    int r_min = p0 / 66;

    u32 AsB = smem_u32(As), BsB = smem_u32(Bs);

    // ldmatrix per-lane address components (constant across chunks)
    int lm = lane >> 3, lr = lane & 7;
    // A: matrices (m&1 -> +8 rows), (m>>1 -> +16B k-offset)
    u32 a_addr[2];
    #pragma unroll
    for (int mt = 0; mt < 2; mt++) {
        int row = wm * 32 + mt * 16 + (lm & 1) * 8 + lr;
        a_addr[mt] = AsB + (u32)(row * (PA * 2)) + (u32)((lm >> 1) * 16);
    }
    // B: per nt-pair q: rows wn*64 + q*16 + (m>>1)*8 + lr ; k-offset (m&1)*16B
    u32 b_addr[4];
    #pragma unroll
    for (int q = 0; q < 4; q++) {
        int row = wn * 64 + q * 16 + (lm >> 1) * 8 + lr;
        b_addr[q] = BsB + (u32)(row * (PA * 2)) + (u32)((lm & 1) * 16);
    }

    // A-build constants: thread handles pixel apix, k-half akh
    int apix = tid >> 1, akh = tid & 1;
    int ap = p0 + apix;
    int ar = ap / 66, ac = ap - ar * 66;
    if (ap >= NPIX) { ar = r_min; ac = 0; }          // safe dummy
    int abase = (ar - r_min) * 70 + ac;

    float acc[2][8][4];
    #pragma unroll
    for (int mt = 0; mt < 2; mt++)
        #pragma unroll
        for (int nt = 0; nt < 8; nt++)
            #pragma unroll
            for (int q = 0; q < 4; q++) acc[mt][nt][q] = 0.f;

    const __half* xsb = g_xs + ((size_t)b << 21);

    for (int i = 0; i < 144; i++) {
        int k0 = i * 32;
        int ci_lo = k0 / 9;
        __syncthreads();   // previous iter's reads done

        // ---- stage halo ----
        #pragma unroll 1
        for (int e = tid; e < 1750; e += 256) {
            int dci = e / 350; int rem = e - dci * 350;
            int ry = rem / 70;  int cx = rem - ry * 70;
            int ci = ci_lo + dci;
            int gr = r_min - 2 + ry, gc = cx - 2;
            __half v = __float2half_rn(0.f);
            if (ci < 512 && (unsigned)gr < 64u && (unsigned)gc < 64u)
                v = xsb[((size_t)ci << 12) + (gr << 6) + gc];
            Hs[e] = v;
        }
        // ---- stage B (pure copy): row=tid>>1, two 16B segs ----
        {
            int brow = tid >> 1, bs2 = (tid & 1) * 2;
            const __half* bsrc = g_wtB + (size_t)(o0 + brow) * KTOT + k0;
            *(float4*)&Bs[brow * PA + bs2 * 8]       = *(const float4*)(bsrc + bs2 * 8);
            *(float4*)&Bs[brow * PA + (bs2 + 1) * 8] = *(const float4*)(bsrc + (bs2 + 1) * 8);
        }
        // ---- k -> halo-offset table ----
        if (tid < 32) {
            int kg = k0 + tid;
            int ci = kg / 9; int t9 = kg - 9 * ci;
            int ky = t9 / 3; int kx = t9 - 3 * ky;
            offs_sh[tid] = (u32)((ci - ci_lo) * 350 + ky * 70 + kx);
        }
        __syncthreads();

        // ---- build A-tile: 16 halves per thread ----
        {
            __half* arow = &As[apix * PA + akh * 16];
            int ob = akh * 16;
            #pragma unroll
            for (int j = 0; j < 8; j++) {
                __half v0 = Hs[abase + offs_sh[ob + 2 * j]];
                __half v1 = Hs[abase + offs_sh[ob + 2 * j + 1]];
                ((__half2*)arow)[j] = __halves2half2(v0, v1);
            }
        }
        __syncthreads();

        // ---- LDSM + HMMA, 2 k16 slices ----
        #pragma unroll
        for (int sl = 0; sl < 2; sl++) {
            u32 af[2][4];
            #pragma unroll
            for (int mt = 0; mt < 2; mt++)
                ldsm4(af[mt][0], af[mt][1], af[mt][2], af[mt][3],
                      a_addr[mt] + sl * 32);
            u32 bf[8][2];
            #pragma unroll
            for (int q = 0; q < 4; q++) {
                u32 r0, r1, r2, r3;
                ldsm4(r0, r1, r2, r3, b_addr[q] + sl * 32);
                bf[2 * q][0] = r0; bf[2 * q][1] = r1;
                bf[2 * q + 1][0] = r2; bf[2 * q + 1][1] = r3;
            }
            #pragma unroll
            for (int mt = 0; mt < 2; mt++)
                #pragma unroll
                for (int nt = 0; nt < 8; nt++)
                    mma_f16(acc[mt][nt], af[mt][0], af[mt][1], af[mt][2], af[mt][3],
                            bf[nt][0], bf[nt][1]);
        }
    }

    // ---- epilogue: C frags -> g_y[b][o][p] ----
    #pragma unroll
    for (int mt = 0; mt < 2; mt++) {
        int prow0 = p0 + wm * 32 + mt * 16 + g;
        bool ok0 = prow0 < NPIX, ok1 = (prow0 + 8) < NPIX;
        #pragma unroll
        for (int nt = 0; nt < 8; nt++) {
            int o = o0 + wn * 64 + nt * 8 + 2 * tg;
            size_t bo = ((size_t)(b * 512 + o)) * NPIX;
            if (ok0) {
                g_y[bo + prow0] = acc[mt][nt][0];
                g_y[bo + NPIX + prow0] = acc[mt][nt][1];
            }
            if (ok1) {
                g_y[bo + prow0 + 8] = acc[mt][nt][2];
                g_y[bo + NPIX + prow0 + 8] = acc[mt][nt][3];
            }
        }
    }
}

// ---------------- K5: demod --------------------------------------------------
__global__ void k_demod() {
    int wid = (blockIdx.x * 256 + threadIdx.x) >> 5;
    int lane = threadIdx.x & 31;
    int b = wid >> 9, o = wid & 511;
    const float* Ao = g_A + o * 512;
    const float* sbp = g_s + b * 512;
    float acc = 0.f;
    #pragma unroll 4
    for (int i = lane; i < 512; i += 32) {
        float sv = sbp[i]; acc = fmaf(Ao[i], sv * sv, acc);
    }
    #pragma unroll
    for (int s = 16; s; s >>= 1) acc += __shfl_xor_sync(0xFFFFFFFFu, acc, s);
    if (lane == 0) g_d[wid] = rsqrtf(acc + 1e-8f);
}

// ---------------- K6: demod+bias -> up-FIR -> act -> down-FIR ----------------
__global__ __launch_bounds__(256) void k_fir(const float* __restrict__ upf,
                                             const float* __restrict__ dnf,
                                             const float* __restrict__ cb,
                                             float* __restrict__ out) {
    extern __shared__ float sm[];
    float* sfu  = sm;
    float* sfd  = sm + 12;
    float* simg = sm + 24;
    float* wbuf = simg + 4356;
    float* smid = wbuf + 8 * 204;
    int blk = blockIdx.x;
    int tid = threadIdx.x;
    const float* src = g_y + (size_t)blk * NPIX;
    float dm = g_d[blk];
    float bias = cb[blk & 511];

    if (tid < 12) { sfu[tid] = 2.0f * upf[11 - tid]; sfd[tid] = dnf[11 - tid]; }
    for (int e = tid; e < NPIX; e += 256) simg[e] = src[e] * dm + bias;
    __syncthreads();

    int warp = tid >> 5, lane = tid & 31;
    float* vrow = wbuf + warp * 204;
    float* hrow = vrow + 66;

    for (int rr = warp; rr < SUP; rr += 8) {
        int tv0 = (rr & 1) ^ 1;
        for (int c = lane; c < 66; c += 32) {
            float a = 0.f;
            for (int t = tv0; t < 12; t += 2) {
                int j = rr + t - 9;
                if (j >= 0 && j <= 130) a = fmaf(sfu[t], simg[(j >> 1) * 66 + c], a);
            }
            vrow[c] = a;
        }
        __syncwarp();
        for (int q = lane; q < SUP; q += 32) {
            float a = 0.f;
            int t0 = (q & 1) ^ 1;
            for (int t = t0; t < 12; t += 2) {
                int j = q + t - 9;
                if (j >= 0 && j <= 130) a = fmaf(sfu[t], vrow[j >> 1], a);
            }
            a = (a >= 0.f ? a : 0.2f * a) * 1.4142135623730951f;
            a = fminf(fmaxf(a, -256.f), 256.f);
            hrow[q] = a;
        }
        __syncwarp();
        for (int p2 = lane; p2 < 64; p2 += 32) {
            float a = 0.f;
            #pragma unroll
            for (int t = 0; t < 12; t++) a = fmaf(sfd[t], hrow[2 * p2 + t], a);
            smid[rr * 64 + p2] = a;
        }
        __syncwarp();
    }
    __syncthreads();

    float* dst = out + (size_t)blk * 4096;
    for (int e = tid; e < 4096; e += 256) {
        int p2 = e >> 6, c = e & 63;
        float a = 0.f;
        #pragma unroll
        for (int t = 0; t < 12; t++) a = fmaf(sfd[t], smid[(2 * p2 + t) * 64 + c], a);
        dst[e] = a;
    }
}

// ---------------- launch -----------------------------------------------------
extern "C" void kernel_launch(void* const* d_in, const int* in_sizes, int n_in,
                              void* d_out, int out_size) {
    const float* x  = (const float*)d_in[0];
    const float* w  = (const float*)d_in[1];
    const float* aw = (const float*)d_in[2];
    const float* ab = (const float*)d_in[3];
    const float* cw = (const float*)d_in[4];
    const float* cb = (const float*)d_in[5];
    const float* uf = (const float*)d_in[6];
    const float* df = (const float*)d_in[7];
    float* out = (float*)d_out;

    k_pre<<<1024, 256>>>(cw, w, aw, ab);            // 1 (wt + styles)
    k_norm_styles<<<1, 256>>>();                    // 2
    k_xs<<<32768, 256>>>(x);                        // 3

    dim3 cgrid(35, 4, BATCH);
    k_conv<<<cgrid, 256>>>();                       // 4 <-- profiled slot

    k_demod<<<512, 256>>>();                        // 5

    const int fir_smem = (24 + 4356 + 8 * 204 + 8832) * (int)sizeof(float);
    cudaFuncSetAttribute(k_fir, cudaFuncAttributeMaxDynamicSharedMemorySize, fir_smem);
    k_fir<<<BATCH * CH, 256, fir_smem>>>(uf, df, cb, out); // 6
}

// round 8
// speedup vs baseline: 4.8422x; 1.8033x over previous
#include <cuda_runtime.h>
#include <cuda_fp16.h>
#include <math.h>

#define BATCH 8
#define CH    512
#define NPIX  4356          // 66*66
#define SUP   138
#define KTOT  4608
#define PA    40            // smem tile pitch in halves (80B rows, LDSM conflict-free)

typedef unsigned int u32;
typedef unsigned long long u64;

// ---------------- scratch (device globals) ----------------------------------
__device__ float g_styles[BATCH * CH];
__device__ float g_s[BATCH * CH];
__device__ __align__(16) __half g_xs[(size_t)BATCH * CH * 4096];  // half(x*s)
__device__ __align__(16) __half g_wtB[(size_t)CH * KTOT];         // half(wt) [o][k]
__device__ float g_A[CH * CH];
__device__ float g_d[BATCH * CH];
__device__ __align__(16) float g_y[(size_t)BATCH * CH * NPIX];    // conv out [b][o][p]

__device__ __forceinline__ void ldsm4(u32& r0, u32& r1, u32& r2, u32& r3, u32 addr) {
    asm volatile("ldmatrix.sync.aligned.m8n8.x4.shared.b16 {%0,%1,%2,%3}, [%4];"
        : "=r"(r0), "=r"(r1), "=r"(r2), "=r"(r3) : "r"(addr));
}
__device__ __forceinline__ void mma_f16(float* c, u32 a0, u32 a1, u32 a2, u32 a3,
                                        u32 b0, u32 b1) {
    asm volatile("mma.sync.aligned.m16n8k16.row.col.f32.f16.f16.f32 "
        "{%0,%1,%2,%3}, {%4,%5,%6,%7}, {%8,%9}, {%0,%1,%2,%3};"
        : "+f"(c[0]), "+f"(c[1]), "+f"(c[2]), "+f"(c[3])
        : "r"(a0), "r"(a1), "r"(a2), "r"(a3), "r"(b0), "r"(b1));
}
__device__ __forceinline__ u32 smem_u32(const void* p) {
    u32 a; asm("{ .reg .u64 t; cvta.to.shared.u64 t, %1; cvt.u32.u64 %0, t; }"
               : "=r"(a) : "l"(p));
    return a;
}
__device__ __forceinline__ u64 gmem_u64(const void* p) {
    u64 a; asm("cvta.to.global.u64 %0, %1;" : "=l"(a) : "l"(p));
    return a;
}
__device__ __forceinline__ void cpa4(u32 dst, u64 src, u32 srcsz) {
    asm volatile("cp.async.ca.shared.global [%0], [%1], 4, %2;"
                 :: "r"(dst), "l"(src), "r"(srcsz) : "memory");
}
__device__ __forceinline__ void cpa16(u32 dst, u64 src) {
    asm volatile("cp.async.cg.shared.global [%0], [%1], 16;"
                 :: "r"(dst), "l"(src) : "memory");
}
__device__ __forceinline__ void cpa_commit() {
    asm volatile("cp.async.commit_group;" ::: "memory");
}
template <int N> __device__ __forceinline__ void cpa_wait() {
    asm volatile("cp.async.wait_group %0;" :: "n"(N) : "memory");
}

// ---------------- K1 (merged): wt-normalize + styles ------------------------
__global__ void k_pre(const float* __restrict__ cw,
                      const float* __restrict__ w,
                      const float* __restrict__ aw,
                      const float* __restrict__ ab) {
    __shared__ float red[256];
    __shared__ float rsh;
    if (blockIdx.x < 512) {
        int o = blockIdx.x;
        const float* src = cw + (size_t)o * KTOT;
        float ss = 0.f;
        for (int e = threadIdx.x; e < KTOT; e += 256) {
            float v = src[e]; ss = fmaf(v, v, ss);
        }
        red[threadIdx.x] = ss; __syncthreads();
        for (int s = 128; s > 0; s >>= 1) {
            if (threadIdx.x < s) red[threadIdx.x] += red[threadIdx.x + s];
            __syncthreads();
        }
        if (threadIdx.x == 0) rsh = rsqrtf(red[0] * (1.0f / 4608.0f));
        __syncthreads();
        float r = rsh;
        for (int e = threadIdx.x; e < KTOT; e += 256)
            g_wtB[(size_t)o * KTOT + e] = __float2half_rn(src[e] * r);
        float r2 = r * r;
        for (int i = threadIdx.x; i < 512; i += 256) {
            float s9 = 0.f;
            #pragma unroll
            for (int k = 0; k < 9; k++) { float v = src[i * 9 + k]; s9 = fmaf(v, v, s9); }
            g_A[o * 512 + i] = s9 * r2;
        }
    } else {
        int wid = ((blockIdx.x - 512) * 256 + threadIdx.x) >> 5;
        int lane = threadIdx.x & 31;
        int b = wid >> 9, c = wid & 511;
        const float* wr = w + b * 512;
        const float* ar = aw + c * 512;
        float acc = 0.f;
        #pragma unroll 4
        for (int d = lane; d < 512; d += 32) acc = fmaf(wr[d], ar[d], acc);
        #pragma unroll
        for (int s = 16; s; s >>= 1) acc += __shfl_xor_sync(0xFFFFFFFFu, acc, s);
        if (lane == 0) g_styles[wid] = acc * 0.04419417382415922f + ab[c];
    }
}

// ---------------- K2: normalize styles --------------------------------------
__global__ void k_norm_styles() {
    __shared__ float red[256];
    float ss = 0.f;
    for (int i = threadIdx.x; i < 4096; i += 256) {
        float v = g_styles[i]; ss = fmaf(v, v, ss);
    }
    red[threadIdx.x] = ss; __syncthreads();
    for (int s = 128; s > 0; s >>= 1) {
        if (threadIdx.x < s) red[threadIdx.x] += red[threadIdx.x + s];
        __syncthreads();
    }
    float g = rsqrtf(red[0] * (1.0f / 4096.0f));
    for (int i = threadIdx.x; i < 4096; i += 256) g_s[i] = g_styles[i] * g;
}

// ---------------- K3: prescale x -> half(x*s) --------------------------------
__global__ void k_xs(const float* __restrict__ x) {
    int i = blockIdx.x * 256 + threadIdx.x;
    float2 v = ((const float2*)x)[i];
    int cf = i >> 11;
    float s = g_s[cf];
    ((__half2*)g_xs)[i] = __floats2half2_rn(v.x * s, v.y * s);
}

// ---------------- K4: fp16 HMMA conv, cp.async-pipelined ---------------------
// Block: 128 pixels x 128 outs; 8 warps (4m x 2n), warp tile 32x64.
// K in 144 chunks of 32. Halo [5ci][5ry][72cx] + B tile double-buffered via
// cp.async (one commit-group per chunk, wait_group 1).
__global__ __launch_bounds__(256, 2) void k_conv() {
    __shared__ __align__(16) __half Hs[2][1808];      // halo, 4B words all-valid/all-pad
    __shared__ __align__(16) __half As[128 * PA];     // [pix][k] pitch 40
    __shared__ __align__(16) __half Bs[2][128 * PA];  // [o][k]   pitch 40
    __shared__ u32 offs_sh[2][32];

    int tid = threadIdx.x, wid = tid >> 5, lane = tid & 31;
    int g = lane >> 2, tg = lane & 3;
    int wm = wid & 3, wn = wid >> 2;
    int b = blockIdx.z;
    int p0 = blockIdx.x * 128, o0 = blockIdx.y * 128;
    int r_min = p0 / 66;

    u32 AsB = smem_u32(As);
    u32 BsB0 = smem_u32(Bs[0]), BsB1 = smem_u32(Bs[1]);
    u32 HsB0 = smem_u32(Hs[0]), HsB1 = smem_u32(Hs[1]);
    const __half* xsb = g_xs + ((size_t)b << 21);
    u64 xg = gmem_u64(xsb);
    u64 wg = gmem_u64(g_wtB);

    // ldmatrix per-lane addresses (constant)
    int lm = lane >> 3, lr = lane & 7;
    u32 a_addr[2];
    #pragma unroll
    for (int mt = 0; mt < 2; mt++) {
        int row = wm * 32 + mt * 16 + (lm & 1) * 8 + lr;
        a_addr[mt] = AsB + (u32)(row * (PA * 2)) + (u32)((lm >> 1) * 16);
    }
    u32 b_row[4];
    #pragma unroll
    for (int q = 0; q < 4; q++) {
        int row = wn * 64 + q * 16 + (lm >> 1) * 8 + lr;
        b_row[q] = (u32)(row * (PA * 2)) + (u32)((lm & 1) * 16);
    }

    // A-build constants
    int apix = tid >> 1, akh = tid & 1;
    int ap = p0 + apix;
    int ar = ap / 66, ac = ap - ar * 66;
    if (ap >= NPIX) { ar = r_min; ac = 0; }
    int abase = (ar - r_min) * 72 + ac;

    // B staging constants: row = tid>>1, two 16B segs
    int brow = tid >> 1, bseg = (tid & 1) * 2;

    float acc[2][8][4];
    #pragma unroll
    for (int mt = 0; mt < 2; mt++)
        #pragma unroll
        for (int nt = 0; nt < 8; nt++)
            #pragma unroll
            for (int q = 0; q < 4; q++) acc[mt][nt][q] = 0.f;

    // ---- staging: chunk j into buffer j&1 ----
    auto stage = [&](int j) {
        int k0s = j * 32;
        int ci_lo_s = k0s / 9;
        u32 hb = (j & 1) ? HsB1 : HsB0;
        u32 bb = (j & 1) ? BsB1 : BsB0;
        // halo: 900 4B words (dci<5, ry<5, cx2<36)
        #pragma unroll
        for (int q = 0; q < 4; q++) {
            int e4 = tid + q * 256;
            if (e4 < 900) {
                int dci = e4 / 180; int rem = e4 - dci * 180;
                int ry = rem / 36;  int cx2 = rem - ry * 36;
                int ci = ci_lo_s + dci;
                int gr = r_min - 2 + ry, gc = cx2 * 2 - 2;
                bool ok = (ci < 512) & ((unsigned)gr < 64u) & ((unsigned)gc < 63u);
                u32 sz = ok ? 4u : 0u;
                u64 src = xg + (((u64)(u32)ci << 13) + ((u32)gr << 7) + ((u32)(gc & 63) << 1));
                cpa4(hb + (u32)(dci * 720 + ry * 144 + cx2 * 4), src, sz);
            }
        }
        // B tile: 128 rows x 64B
        u64 bsrc = wg + (((u64)(u32)(o0 + brow)) * (KTOT * 2) + (u32)(k0s * 2));
        cpa16(bb + (u32)(brow * (PA * 2) + bseg * 16), bsrc + bseg * 16);
        cpa16(bb + (u32)(brow * (PA * 2) + (bseg + 1) * 16), bsrc + (bseg + 1) * 16);
        // k -> halo-offset table
        if (tid < 32) {
            int kg = k0s + tid;
            int ci = kg / 9; int t9 = kg - 9 * ci;
            int ky = t9 / 3; int kx = t9 - 3 * ky;
            offs_sh[j & 1][tid] = (u32)((ci - ci_lo_s) * 360 + ky * 72 + kx);
        }
        cpa_commit();
    };

    stage(0);

    for (int i = 0; i < 144; i++) {
        int cur = i & 1;
        if (i + 1 < 144) { stage(i + 1); cpa_wait<1>(); }
        else             { cpa_wait<0>(); }
        __syncthreads();   // halo[cur]/Bs[cur] visible; prev LDSM reads of As done

        // ---- build A-tile from halo[cur] ----
        {
            const __half* hp = Hs[cur];
            const u32* ofs = offs_sh[cur];
            __half* arow = &As[apix * PA + akh * 16];
            int ob = akh * 16;
            #pragma unroll
            for (int j = 0; j < 8; j++) {
                __half v0 = hp[abase + ofs[ob + 2 * j]];
                __half v1 = hp[abase + ofs[ob + 2 * j + 1]];
                ((__half2*)arow)[j] = __halves2half2(v0, v1);
            }
        }
        __syncthreads();

        // ---- LDSM + HMMA ----
        u32 bbase = cur ? BsB1 : BsB0;
        #pragma unroll
        for (int sl = 0; sl < 2; sl++) {
            u32 af[2][4];
            #pragma unroll
            for (int mt = 0; mt < 2; mt++)
                ldsm4(af[mt][0], af[mt][1], af[mt][2], af[mt][3],
                      a_addr[mt] + sl * 32);
            u32 bf[8][2];
            #pragma unroll
            for (int q = 0; q < 4; q++) {
                u32 r0, r1, r2, r3;
                ldsm4(r0, r1, r2, r3, bbase + b_row[q] + sl * 32);
                bf[2 * q][0] = r0; bf[2 * q][1] = r1;
                bf[2 * q + 1][0] = r2; bf[2 * q + 1][1] = r3;
            }
            #pragma unroll
            for (int mt = 0; mt < 2; mt++)
                #pragma unroll
                for (int nt = 0; nt < 8; nt++)
                    mma_f16(acc[mt][nt], af[mt][0], af[mt][1], af[mt][2], af[mt][3],
                            bf[nt][0], bf[nt][1]);
        }
    }

    // ---- epilogue ----
    #pragma unroll
    for (int mt = 0; mt < 2; mt++) {
        int prow0 = p0 + wm * 32 + mt * 16 + g;
        bool ok0 = prow0 < NPIX, ok1 = (prow0 + 8) < NPIX;
        #pragma unroll
        for (int nt = 0; nt < 8; nt++) {
            int o = o0 + wn * 64 + nt * 8 + 2 * tg;
            size_t bo = ((size_t)(b * 512 + o)) * NPIX;
            if (ok0) {
                g_y[bo + prow0] = acc[mt][nt][0];
                g_y[bo + NPIX + prow0] = acc[mt][nt][1];
            }
            if (ok1) {
                g_y[bo + prow0 + 8] = acc[mt][nt][2];
                g_y[bo + NPIX + prow0 + 8] = acc[mt][nt][3];
            }
        }
    }
}

// ---------------- K5: demod --------------------------------------------------
__global__ void k_demod() {
    int wid = (blockIdx.x * 256 + threadIdx.x) >> 5;
    int lane = threadIdx.x & 31;
    int b = wid >> 9, o = wid & 511;
    const float* Ao = g_A + o * 512;
    const float* sbp = g_s + b * 512;
    float acc = 0.f;
    #pragma unroll 4
    for (int i = lane; i < 512; i += 32) {
        float sv = sbp[i]; acc = fmaf(Ao[i], sv * sv, acc);
    }
    #pragma unroll
    for (int s = 16; s; s >>= 1) acc += __shfl_xor_sync(0xFFFFFFFFu, acc, s);
    if (lane == 0) g_d[wid] = rsqrtf(acc + 1e-8f);
}

// ---------------- K6: demod+bias -> up-FIR -> act -> down-FIR ----------------
__global__ __launch_bounds__(256) void k_fir(const float* __restrict__ upf,
                                             const float* __restrict__ dnf,
                                             const float* __restrict__ cb,
                                             float* __restrict__ out) {
    extern __shared__ float sm[];
    float* sfu  = sm;
    float* sfd  = sm + 12;
    float* simg = sm + 24;
    float* wbuf = simg + 4356;
    float* smid = wbuf + 8 * 204;
    int blk = blockIdx.x;
    int tid = threadIdx.x;
    const float* src = g_y + (size_t)blk * NPIX;
    float dm = g_d[blk];
    float bias = cb[blk & 511];

    if (tid < 12) { sfu[tid] = 2.0f * upf[11 - tid]; sfd[tid] = dnf[11 - tid]; }
    for (int e = tid; e < NPIX; e += 256) simg[e] = src[e] * dm + bias;
    __syncthreads();

    int warp = tid >> 5, lane = tid & 31;
    float* vrow = wbuf + warp * 204;
    float* hrow = vrow + 66;

    for (int rr = warp; rr < SUP; rr += 8) {
        int tv0 = (rr & 1) ^ 1;
        for (int c = lane; c < 66; c += 32) {
            float a = 0.f;
            for (int t = tv0; t < 12; t += 2) {
                int j = rr + t - 9;
                if (j >= 0 && j <= 130) a = fmaf(sfu[t], simg[(j >> 1) * 66 + c], a);
            }
            vrow[c] = a;
        }
        __syncwarp();
        for (int q = lane; q < SUP; q += 32) {
            float a = 0.f;
            int t0 = (q & 1) ^ 1;
            for (int t = t0; t < 12; t += 2) {
                int j = q + t - 9;
                if (j >= 0 && j <= 130) a = fmaf(sfu[t], vrow[j >> 1], a);
            }
            a = (a >= 0.f ? a : 0.2f * a) * 1.4142135623730951f;
            a = fminf(fmaxf(a, -256.f), 256.f);
            hrow[q] = a;
        }
        __syncwarp();
        for (int p2 = lane; p2 < 64; p2 += 32) {
            float a = 0.f;
            #pragma unroll
            for (int t = 0; t < 12; t++) a = fmaf(sfd[t], hrow[2 * p2 + t], a);
            smid[rr * 64 + p2] = a;
        }
        __syncwarp();
    }
    __syncthreads();

    float* dst = out + (size_t)blk * 4096;
    for (int e = tid; e < 4096; e += 256) {
        int p2 = e >> 6, c = e & 63;
        float a = 0.f;
        #pragma unroll
        for (int t = 0; t < 12; t++) a = fmaf(sfd[t], smid[(2 * p2 + t) * 64 + c], a);
        dst[e] = a;
    }
}

// ---------------- launch -----------------------------------------------------
extern "C" void kernel_launch(void* const* d_in, const int* in_sizes, int n_in,
                              void* d_out, int out_size) {
    const float* x  = (const float*)d_in[0];
    const float* w  = (const float*)d_in[1];
    const float* aw = (const float*)d_in[2];
    const float* ab = (const float*)d_in[3];
    const float* cw = (const float*)d_in[4];
    const float* cb = (const float*)d_in[5];
    const float* uf = (const float*)d_in[6];
    const float* df = (const float*)d_in[7];
    float* out = (float*)d_out;

    k_pre<<<1024, 256>>>(cw, w, aw, ab);            // 1
    k_norm_styles<<<1, 256>>>();                    // 2
    k_xs<<<32768, 256>>>(x);                        // 3

    dim3 cgrid(35, 4, BATCH);
    k_conv<<<cgrid, 256>>>();                       // 4 <-- profiled slot

    k_demod<<<512, 256>>>();                        // 5

    const int fir_smem = (24 + 4356 + 8 * 204 + 8832) * (int)sizeof(float);
    cudaFuncSetAttribute(k_fir, cudaFuncAttributeMaxDynamicSharedMemorySize, fir_smem);
    k_fir<<<BATCH * CH, 256, fir_smem>>>(uf, df, cb, out); // 6
}